// round 13
// baseline (speedup 1.0000x reference)
#include <cuda_runtime.h>

#define BB 32
#define NN 2048
#define EPSF 5e-4f
#define HH 5.0f
#define MC 28            /* Chebyshev-Gauss nodes; degree 27 */

typedef unsigned long long u64;

#define FMA2(d,a,b,c) asm("fma.rn.f32x2 %0,%1,%2,%3;" : "=l"(d) : "l"(a),"l"(b),"l"(c))
#define SUB2(d,a,b)   asm("sub.rn.f32x2 %0,%1,%2;"    : "=l"(d) : "l"(a),"l"(b))
#define PK2(d,lo,hi)  asm("mov.b64 %0,{%1,%2};" : "=l"(d) : "r"(__float_as_uint(lo)), "r"(__float_as_uint(hi)))
#define UPK2(lo,hi,s) do { unsigned _a,_b; asm("mov.b64 {%0,%1},%2;" : "=r"(_a),"=r"(_b) : "l"(s)); lo=__uint_as_float(_a); hi=__uint_as_float(_b); } while(0)

__device__ float g_Fp[BB*3*32];   // node partials from helper blocks 1..3
__device__ float g_rowSum[BB];
__device__ int   g_rowCtr[BB];    // zero-init; finisher resets
__device__ int   g_ctr;           // zero-init; self-resetting

// Grid (4, BB) x 512 = 128 blocks -> single wave, one block per SM.
//  blk 1..3: pair partials for scores [blk*512, +512): paired sigmoid at node
//            W=e^{x_k}: sig(a)+sig(b) = (2ab+pW)/(ab+pW+W^2). Write, arrive.
//  blk 0   : finisher AND pair worker for chunk 0. Preloads all scores/labels,
//            does its pair chunk + histogram + rank-based maxDCG (overlapped
//            with helpers), spins on row counter, folds partials, DCT-II,
//            packed-f32x2 Clenshaw (4 pts/thread), row sum; last row -> mean.
__global__ __launch_bounds__(512, 2)
void fused(const float* __restrict__ yp, const float* __restrict__ yt,
           float* __restrict__ out) {
    int blk = blockIdx.x, b = blockIdx.y;
    int t = threadIdx.x, w = t >> 5, lane = t & 31;

    __shared__ float2 sP[256];
    __shared__ float sF[16*33];
    __shared__ float sFn[32];
    __shared__ float2 sC2[MC];        // coefs duplicated (lo==hi) for f32x2
    __shared__ float sRed[16];
    __shared__ unsigned long long sH[16];
    __shared__ int sOff[4];
    __shared__ float sInv;

    // node for this lane: x_k = HH*cos(pi(2k+1)/(2*MC)); lanes>=MC junk, unread
    float W  = __expf(HH * cospif((float)(2*lane + 1) * (1.0f/(2*MC))));
    float W2 = W * W;

    if (blk != 0) {
        // ------------------ helper pair blocks (chunks 1..3) ------------------
        if (t < 256) {
            float2 sc = ((const float2*)(yp + b*NN + blk*512))[t];
            float ea = __expf(sc.x), eb = __expf(sc.y);
            sP[t] = make_float2(ea + eb, 2.f*ea*eb);
        }
        __syncthreads();
        const float4* P4 = (const float4*)(sP + w*16);   // (p0,r0,p1,r1) x8
        float acc = 0.f;
        #pragma unroll
        for (int i = 0; i < 8; i++) {
            float4 q = P4[i];
            acc = fmaf(fmaf(q.x, W, q.y),
                       __frcp_rn(fmaf(q.x, W, fmaf(0.5f, q.y, W2))), acc);
            acc = fmaf(fmaf(q.z, W, q.w),
                       __frcp_rn(fmaf(q.z, W, fmaf(0.5f, q.w, W2))), acc);
        }
        sF[w*33 + lane] = acc;
        __syncthreads();
        if (w == 0) {
            float F = 0.f;
            #pragma unroll
            for (int i = 0; i < 16; i++) F += sF[i*33 + lane];
            g_Fp[(b*3 + (blk - 1))*32 + lane] = F;
        }
        __syncthreads();
        if (t == 0) {
            __threadfence();
            atomicAdd(&g_rowCtr[b], 1);
        }
        return;
    }

    // -------------------- finisher block (also chunk 0) --------------------
    float4 s4 = ((const float4*)(yp + b*NN))[t];    // all 2048 scores
    float4 l4 = ((const float4*)(yt + b*NN))[t];    // all 2048 labels
    int vv[4] = {(int)l4.x, (int)l4.y, (int)l4.z, (int)l4.w};

    // chunk-0 pair precompute from the same registers (threads 0..127)
    if (t < 128) {
        float e0 = __expf(s4.x), e1 = __expf(s4.y);
        float e2 = __expf(s4.z), e3 = __expf(s4.w);
        sP[2*t]     = make_float2(e0 + e1, 2.f*e0*e1);
        sP[2*t + 1] = make_float2(e2 + e3, 2.f*e2*e3);
    }
    __syncthreads();
    const float4* P4 = (const float4*)(sP + w*16);
    float acc = 0.f;
    #pragma unroll
    for (int i = 0; i < 8; i++) {
        float4 q = P4[i];
        acc = fmaf(fmaf(q.x, W, q.y),
                   __frcp_rn(fmaf(q.x, W, fmaf(0.5f, q.y, W2))), acc);
        acc = fmaf(fmaf(q.z, W, q.w),
                   __frcp_rn(fmaf(q.z, W, fmaf(0.5f, q.w, W2))), acc);
    }
    sF[w*33 + lane] = acc;

    // packed label histogram (registers only; overlaps pair smem usage)
    unsigned long long pk = (1ULL << (12*vv[0])) + (1ULL << (12*vv[1]))
                          + (1ULL << (12*vv[2])) + (1ULL << (12*vv[3]));
    #pragma unroll
    for (int o = 16; o; o >>= 1) pk += __shfl_xor_sync(0xffffffffu, pk, o);
    if (lane == 0) sH[w] = pk;
    __syncthreads();

    if (w == 0) {            // fold own pair partials -> sFn (own chunk)
        float F = 0.f;
        #pragma unroll
        for (int i = 0; i < 16; i++) F += sF[i*33 + lane];
        sFn[lane] = F;
    } else if (w == 1) {     // fold histogram -> rank boundaries
        unsigned long long hh = (lane < 16) ? sH[lane] : 0ULL;
        #pragma unroll
        for (int o = 8; o; o >>= 1) hh += __shfl_xor_sync(0xffffffffu, hh, o);
        if (lane == 0) {
            int c4 = (int)((hh >> 48) & 0xFFF);
            int c3 = (int)((hh >> 36) & 0xFFF);
            int c2 = (int)((hh >> 24) & 0xFFF);
            int c1 = (int)((hh >> 12) & 0xFFF);
            sOff[0] = c4;  sOff[1] = c4 + c3;
            sOff[2] = c4 + c3 + c2;  sOff[3] = c4 + c3 + c2 + c1;
        }
    }
    __syncthreads();

    // rank-based maxDCG (rank r = n, 0-based); overlapped with helpers
    int B4 = sOff[0], B3 = sOff[1], B2 = sOff[2], B1 = sOff[3];
    float mdcg = 0.f;
    #pragma unroll
    for (int i = 0; i < 4; i++) {
        int n = t + i*512;
        int vr = 4 - (n >= B4) - (n >= B3) - (n >= B2) - (n >= B1);
        mdcg += __fdividef((float)((1 << vr) - 1), __log2f((float)(n + 2)));
    }
    #pragma unroll
    for (int o = 16; o; o >>= 1) mdcg += __shfl_xor_sync(0xffffffffu, mdcg, o);
    if (lane == 0) sRed[w] = mdcg;
    __syncthreads();
    if (t == 0) {
        float x = 0.f;
        #pragma unroll
        for (int i = 0; i < 16; i++) x += sRed[i];
        sInv = 1.0f / fmaxf(x, EPSF);
        // wait for the 3 helper blocks of this row (all co-resident: 128 blocks)
        while (*(volatile int*)&g_rowCtr[b] != 3) __nanosleep(64);
        g_rowCtr[b] = 0;                          // reset for next graph replay
    }
    __syncthreads();
    __threadfence();                              // acquire helper partials

    // fold helper partials into sFn
    if (t < 96) sF[t] = g_Fp[b*96 + t];
    __syncthreads();
    if (t < 32) {
        float F = sFn[t];
        #pragma unroll
        for (int i = 0; i < 3; i++) F += sF[i*32 + t];
        sFn[t] = F;
    }
    __syncthreads();

    // warp-parallel DCT-II: c_m = (2/MC) sum_k F_k cos(pi m(2k+1)/(2MC));
    // written duplicated into float2 for packed Clenshaw.
    float Fk = (lane < MC) ? sFn[lane] : 0.f;
    if (w < 14) {
        #pragma unroll
        for (int j = 0; j < 2; j++) {
            int m = w + 14*j;
            float term = Fk * cospif((float)(m*(2*lane + 1)) * (1.0f/(2*MC)));
            #pragma unroll
            for (int o = 16; o; o >>= 1) term += __shfl_xor_sync(0xffffffffu, term, o);
            if (lane == 0) {
                float cc = term * (2.0f/MC);
                if (m == 0) cc *= 0.5f;
                sC2[m] = make_float2(cc, cc);
            }
        }
    }
    __syncthreads();

    // packed-f32x2 Clenshaw at 4 points/thread (2 packs)
    float u0 = fminf(fmaxf(s4.x * (1.0f/HH), -1.f), 1.f);
    float u1 = fminf(fmaxf(s4.y * (1.0f/HH), -1.f), 1.f);
    float u2 = fminf(fmaxf(s4.z * (1.0f/HH), -1.f), 1.f);
    float u3 = fminf(fmaxf(s4.w * (1.0f/HH), -1.f), 1.f);
    u64 u01, u23, tu01, tu23;
    PK2(u01,  u0,      u1);
    PK2(u23,  u2,      u3);
    PK2(tu01, u0 + u0, u1 + u1);
    PK2(tu23, u2 + u2, u3 + u3);
    u64 y1a = 0ULL, y2a = 0ULL, y1b = 0ULL, y2b = 0ULL;
    #pragma unroll
    for (int m = MC - 1; m >= 1; m--) {
        u64 cd = *reinterpret_cast<const u64*>(&sC2[m]);
        u64 ta, tb;
        FMA2(ta, tu01, y1a, cd); SUB2(ta, ta, y2a); y2a = y1a; y1a = ta;
        FMA2(tb, tu23, y1b, cd); SUB2(tb, tb, y2b); y2b = y1b; y1b = tb;
    }
    u64 cd0 = *reinterpret_cast<const u64*>(&sC2[0]);
    u64 Fa, Fb;
    FMA2(Fa, u01, y1a, cd0); SUB2(Fa, Fa, y2a);
    FMA2(Fb, u23, y1b, cd0); SUB2(Fb, Fb, y2b);
    float F0, F1, F2, F3;
    UPK2(F0, F1, Fa);
    UPK2(F2, F3, Fb);

    float FF[4] = {F0, F1, F2, F3};
    float numer = 0.f;
    #pragma unroll
    for (int i = 0; i < 4; i++) {
        float gain = (float)((1 << vv[i]) - 1);
        numer += __fdividef(gain, __log2f(1.5f + FF[i]));   // pos = 0.5 + F
    }
    #pragma unroll
    for (int o = 16; o; o >>= 1) numer += __shfl_xor_sync(0xffffffffu, numer, o);
    if (lane == 0) sRed[w] = numer;
    __syncthreads();

    if (w == 0) {
        float x = (lane < 16) ? sRed[lane] : 0.f;
        #pragma unroll
        for (int o = 8; o; o >>= 1) x += __shfl_xor_sync(0xffffffffu, x, o);
        int d = 0;
        if (lane == 0) {
            g_rowSum[b] = x * sInv;
            __threadfence();
            d = atomicAdd(&g_ctr, 1);
        }
        d = __shfl_sync(0xffffffffu, d, 0);
        if (d == BB - 1) {                        // last row finisher -> mean
            if (lane == 0) g_ctr = 0;             // self-reset
            __threadfence();
            float v = g_rowSum[lane];
            #pragma unroll
            for (int o = 16; o; o >>= 1) v += __shfl_xor_sync(0xffffffffu, v, o);
            if (lane == 0) out[0] = v * (1.0f/BB);
        }
    }
}

extern "C" void kernel_launch(void* const* d_in, const int* in_sizes, int n_in,
                              void* d_out, int out_size) {
    const float* yp = (const float*)d_in[0];
    const float* yt = (const float*)d_in[1];
    float* out = (float*)d_out;
    (void)in_sizes; (void)n_in; (void)out_size;

    dim3 g(4, BB);
    fused<<<g, 512>>>(yp, yt, out);
}

// round 14
// speedup vs baseline: 1.1308x; 1.1308x over previous
#include <cuda_runtime.h>

#define BB 32
#define NN 2048
#define EPSF 5e-4f
#define HH 5.0f
#define MC 28            /* Chebyshev-Gauss nodes; degree 27 */

typedef unsigned long long u64;

#define FMA2(d,a,b,c) asm("fma.rn.f32x2 %0,%1,%2,%3;" : "=l"(d) : "l"(a),"l"(b),"l"(c))
#define SUB2(d,a,b)   asm("sub.rn.f32x2 %0,%1,%2;"    : "=l"(d) : "l"(a),"l"(b))
#define PK2(d,lo,hi)  asm("mov.b64 %0,{%1,%2};" : "=l"(d) : "r"(__float_as_uint(lo)), "r"(__float_as_uint(hi)))
#define UPK2(lo,hi,s) do { unsigned _a,_b; asm("mov.b64 {%0,%1},%2;" : "=r"(_a),"=r"(_b) : "l"(s)); lo=__uint_as_float(_a); hi=__uint_as_float(_b); } while(0)

__device__ float g_rowSum[BB];
__device__ int   g_ctr;           // zero-init; self-resetting

// Grid (4, BB) x 512, cluster (4,1,1): each row's 4 CTAs form a cluster.
//  rank 1..3: pair partials for scores [rank*512, +512): paired sigmoid at
//             node W=e^{x_k}: sig(a)+sig(b) = (2ab+pW)/(ab+pW+W^2).
//             Partials pushed into rank0's smem via st.shared::cluster,
//             then mbarrier.arrive.release.cluster. No globals, no fences.
//  rank 0   : finisher AND pair worker chunk 0. Overlapped with helpers:
//             preload all scores/labels, own pair chunk, histogram ->
//             rank-based maxDCG -> inv. Then poll local mbarrier (acquire
//             cluster), fold from LOCAL smem, warp-parallel DCT-II,
//             packed-f32x2 Clenshaw (4 pts/thread), row sum; last row -> mean.
__global__ __launch_bounds__(512, 2) __cluster_dims__(4, 1, 1)
void fused(const float* __restrict__ yp, const float* __restrict__ yt,
           float* __restrict__ out) {
    int blk = blockIdx.x, b = blockIdx.y;     // blk == cluster rank (dim x = 4)
    int t = threadIdx.x, w = t >> 5, lane = t & 31;

    __shared__ float2 sP[256];
    __shared__ float sF[16*33];
    __shared__ float sPart[3*32];     // helper partials land here (rank 0)
    __shared__ float sFn[32];
    __shared__ float2 sC2[MC];        // coefs duplicated (lo==hi) for f32x2
    __shared__ float sRed[16];
    __shared__ unsigned long long sH[16];
    __shared__ int sOff[4];
    __shared__ float sInv;
    __shared__ __align__(8) unsigned long long sMbar;

    // node for this lane: x_k = HH*cos(pi(2k+1)/(2*MC)); lanes>=MC junk, unread
    float W  = __expf(HH * cospif((float)(2*lane + 1) * (1.0f/(2*MC))));
    float W2 = W * W;

    if (blk == 0) {
        if (t == 0) {
            unsigned mb = (unsigned)__cvta_generic_to_shared(&sMbar);
            asm volatile("mbarrier.init.shared.b64 [%0], 3;" :: "r"(mb) : "memory");
        }
        __syncthreads();                      // mbar init before cluster arrive
    }
    // split cluster barrier: arrive now (release: publishes mbar init),
    // wait later where each role actually needs peers.
    asm volatile("barrier.cluster.arrive.aligned;" ::: "memory");

    if (blk != 0) {
        // ------------------ helper pair blocks (chunks 1..3) ------------------
        if (t < 256) {
            float2 sc = ((const float2*)(yp + b*NN + blk*512))[t];
            float ea = __expf(sc.x), eb = __expf(sc.y);
            sP[t] = make_float2(ea + eb, 2.f*ea*eb);
        }
        __syncthreads();
        const float4* P4 = (const float4*)(sP + w*16);   // (p0,r0,p1,r1) x8
        float acc = 0.f;
        #pragma unroll
        for (int i = 0; i < 8; i++) {
            float4 q = P4[i];
            acc = fmaf(fmaf(q.x, W, q.y),
                       __frcp_rn(fmaf(q.x, W, fmaf(0.5f, q.y, W2))), acc);
            acc = fmaf(fmaf(q.z, W, q.w),
                       __frcp_rn(fmaf(q.z, W, fmaf(0.5f, q.w, W2))), acc);
        }
        sF[w*33 + lane] = acc;
        __syncthreads();
        // everyone waits for cluster start-fence (finisher's mbar is live)
        asm volatile("barrier.cluster.wait.aligned;" ::: "memory");
        if (w == 0) {
            float F = 0.f;
            #pragma unroll
            for (int i = 0; i < 16; i++) F += sF[i*33 + lane];
            // push partial straight into finisher's sPart via DSMEM
            unsigned loc = (unsigned)__cvta_generic_to_shared(&sPart[(blk - 1)*32 + lane]);
            unsigned rem;
            asm("mapa.shared::cluster.u32 %0, %1, %2;" : "=r"(rem) : "r"(loc), "r"(0));
            asm volatile("st.shared::cluster.f32 [%0], %1;" :: "r"(rem), "f"(F) : "memory");
            __syncwarp();
            if (lane == 0) {
                unsigned mbl = (unsigned)__cvta_generic_to_shared(&sMbar);
                unsigned mbr;
                asm("mapa.shared::cluster.u32 %0, %1, %2;" : "=r"(mbr) : "r"(mbl), "r"(0));
                asm volatile("mbarrier.arrive.release.cluster.shared::cluster.b64 _, [%0];"
                             :: "r"(mbr) : "memory");
            }
        }
        return;
    }

    // -------------------- finisher block (also chunk 0) --------------------
    float4 s4 = ((const float4*)(yp + b*NN))[t];    // all 2048 scores
    float4 l4 = ((const float4*)(yt + b*NN))[t];    // all 2048 labels
    int vv[4] = {(int)l4.x, (int)l4.y, (int)l4.z, (int)l4.w};

    // chunk-0 pair precompute from the same registers (threads 0..127)
    if (t < 128) {
        float e0 = __expf(s4.x), e1 = __expf(s4.y);
        float e2 = __expf(s4.z), e3 = __expf(s4.w);
        sP[2*t]     = make_float2(e0 + e1, 2.f*e0*e1);
        sP[2*t + 1] = make_float2(e2 + e3, 2.f*e2*e3);
    }
    __syncthreads();
    const float4* P4 = (const float4*)(sP + w*16);
    float acc = 0.f;
    #pragma unroll
    for (int i = 0; i < 8; i++) {
        float4 q = P4[i];
        acc = fmaf(fmaf(q.x, W, q.y),
                   __frcp_rn(fmaf(q.x, W, fmaf(0.5f, q.y, W2))), acc);
        acc = fmaf(fmaf(q.z, W, q.w),
                   __frcp_rn(fmaf(q.z, W, fmaf(0.5f, q.w, W2))), acc);
    }
    sF[w*33 + lane] = acc;

    // packed label histogram (registers only)
    unsigned long long pk = (1ULL << (12*vv[0])) + (1ULL << (12*vv[1]))
                          + (1ULL << (12*vv[2])) + (1ULL << (12*vv[3]));
    #pragma unroll
    for (int o = 16; o; o >>= 1) pk += __shfl_xor_sync(0xffffffffu, pk, o);
    if (lane == 0) sH[w] = pk;
    __syncthreads();

    if (w == 0) {            // fold own pair partials -> sFn (own chunk)
        float F = 0.f;
        #pragma unroll
        for (int i = 0; i < 16; i++) F += sF[i*33 + lane];
        sFn[lane] = F;
    } else if (w == 1) {     // fold histogram -> rank boundaries
        unsigned long long hh = (lane < 16) ? sH[lane] : 0ULL;
        #pragma unroll
        for (int o = 8; o; o >>= 1) hh += __shfl_xor_sync(0xffffffffu, hh, o);
        if (lane == 0) {
            int c4 = (int)((hh >> 48) & 0xFFF);
            int c3 = (int)((hh >> 36) & 0xFFF);
            int c2 = (int)((hh >> 24) & 0xFFF);
            int c1 = (int)((hh >> 12) & 0xFFF);
            sOff[0] = c4;  sOff[1] = c4 + c3;
            sOff[2] = c4 + c3 + c2;  sOff[3] = c4 + c3 + c2 + c1;
        }
    }
    __syncthreads();

    // rank-based maxDCG (rank r = n, 0-based); overlapped with helpers
    int B4 = sOff[0], B3 = sOff[1], B2 = sOff[2], B1 = sOff[3];
    float mdcg = 0.f;
    #pragma unroll
    for (int i = 0; i < 4; i++) {
        int n = t + i*512;
        int vr = 4 - (n >= B4) - (n >= B3) - (n >= B2) - (n >= B1);
        mdcg += __fdividef((float)((1 << vr) - 1), __log2f((float)(n + 2)));
    }
    #pragma unroll
    for (int o = 16; o; o >>= 1) mdcg += __shfl_xor_sync(0xffffffffu, mdcg, o);
    if (lane == 0) sRed[w] = mdcg;
    __syncthreads();

    // drain cluster start-fence, then wait for the 3 helper arrivals
    asm volatile("barrier.cluster.wait.aligned;" ::: "memory");
    if (t == 0) {
        float x = 0.f;
        #pragma unroll
        for (int i = 0; i < 16; i++) x += sRed[i];
        sInv = 1.0f / fmaxf(x, EPSF);
        unsigned mb = (unsigned)__cvta_generic_to_shared(&sMbar);
        asm volatile(
            "{\n\t.reg .pred P;\n\t"
            "W%=:\n\t"
            "mbarrier.try_wait.parity.acquire.cluster.shared::cta.b64 P, [%0], 0;\n\t"
            "@P bra D%=;\n\t"
            "bra W%=;\n\t"
            "D%=:\n\t}"
            :: "r"(mb) : "memory");
    }
    __syncthreads();                  // helper partials now visible in sPart

    if (t < 32) {
        float F = sFn[t];
        #pragma unroll
        for (int i = 0; i < 3; i++) F += sPart[i*32 + t];
        sFn[t] = F;
    }
    __syncthreads();

    // warp-parallel DCT-II: c_m = (2/MC) sum_k F_k cos(pi m(2k+1)/(2MC));
    // written duplicated into float2 for packed Clenshaw.
    float Fk = (lane < MC) ? sFn[lane] : 0.f;
    if (w < 14) {
        #pragma unroll
        for (int j = 0; j < 2; j++) {
            int m = w + 14*j;
            float term = Fk * cospif((float)(m*(2*lane + 1)) * (1.0f/(2*MC)));
            #pragma unroll
            for (int o = 16; o; o >>= 1) term += __shfl_xor_sync(0xffffffffu, term, o);
            if (lane == 0) {
                float cc = term * (2.0f/MC);
                if (m == 0) cc *= 0.5f;
                sC2[m] = make_float2(cc, cc);
            }
        }
    }
    __syncthreads();

    // packed-f32x2 Clenshaw at 4 points/thread (2 packs)
    float u0 = fminf(fmaxf(s4.x * (1.0f/HH), -1.f), 1.f);
    float u1 = fminf(fmaxf(s4.y * (1.0f/HH), -1.f), 1.f);
    float u2 = fminf(fmaxf(s4.z * (1.0f/HH), -1.f), 1.f);
    float u3 = fminf(fmaxf(s4.w * (1.0f/HH), -1.f), 1.f);
    u64 u01, u23, tu01, tu23;
    PK2(u01,  u0,      u1);
    PK2(u23,  u2,      u3);
    PK2(tu01, u0 + u0, u1 + u1);
    PK2(tu23, u2 + u2, u3 + u3);
    u64 y1a = 0ULL, y2a = 0ULL, y1b = 0ULL, y2b = 0ULL;
    #pragma unroll
    for (int m = MC - 1; m >= 1; m--) {
        u64 cd = *reinterpret_cast<const u64*>(&sC2[m]);
        u64 ta, tb;
        FMA2(ta, tu01, y1a, cd); SUB2(ta, ta, y2a); y2a = y1a; y1a = ta;
        FMA2(tb, tu23, y1b, cd); SUB2(tb, tb, y2b); y2b = y1b; y1b = tb;
    }
    u64 cd0 = *reinterpret_cast<const u64*>(&sC2[0]);
    u64 Fa, Fb;
    FMA2(Fa, u01, y1a, cd0); SUB2(Fa, Fa, y2a);
    FMA2(Fb, u23, y1b, cd0); SUB2(Fb, Fb, y2b);
    float F0, F1, F2, F3;
    UPK2(F0, F1, Fa);
    UPK2(F2, F3, Fb);

    float FF[4] = {F0, F1, F2, F3};
    float numer = 0.f;
    #pragma unroll
    for (int i = 0; i < 4; i++) {
        float gain = (float)((1 << vv[i]) - 1);
        numer += __fdividef(gain, __log2f(1.5f + FF[i]));   // pos = 0.5 + F
    }
    #pragma unroll
    for (int o = 16; o; o >>= 1) numer += __shfl_xor_sync(0xffffffffu, numer, o);
    if (lane == 0) sRed[w] = numer;
    __syncthreads();

    if (w == 0) {
        float x = (lane < 16) ? sRed[lane] : 0.f;
        #pragma unroll
        for (int o = 8; o; o >>= 1) x += __shfl_xor_sync(0xffffffffu, x, o);
        int d = 0;
        if (lane == 0) {
            g_rowSum[b] = x * sInv;
            __threadfence();
            d = atomicAdd(&g_ctr, 1);
        }
        d = __shfl_sync(0xffffffffu, d, 0);
        if (d == BB - 1) {                        // last row finisher -> mean
            if (lane == 0) g_ctr = 0;             // self-reset
            __threadfence();
            float v = g_rowSum[lane];
            #pragma unroll
            for (int o = 16; o; o >>= 1) v += __shfl_xor_sync(0xffffffffu, v, o);
            if (lane == 0) out[0] = v * (1.0f/BB);
        }
    }
}

extern "C" void kernel_launch(void* const* d_in, const int* in_sizes, int n_in,
                              void* d_out, int out_size) {
    const float* yp = (const float*)d_in[0];
    const float* yt = (const float*)d_in[1];
    float* out = (float*)d_out;
    (void)in_sizes; (void)n_in; (void)out_size;

    dim3 g(4, BB);
    fused<<<g, 512>>>(yp, yt, out);
}

// round 15
// speedup vs baseline: 1.1577x; 1.0238x over previous
#include <cuda_runtime.h>

#define BB 32
#define NN 2048
#define EPSF 5e-4f
#define HH 5.0f
#define MC 28            /* Chebyshev-Gauss nodes; degree 27 */
#define FCH 128          /* finisher pair-chunk size */
#define HCH 640          /* helper pair-chunk size (128 + 3*640 = 2048) */

typedef unsigned long long u64;

#define FMA2(d,a,b,c) asm("fma.rn.f32x2 %0,%1,%2,%3;" : "=l"(d) : "l"(a),"l"(b),"l"(c))
#define SUB2(d,a,b)   asm("sub.rn.f32x2 %0,%1,%2;"    : "=l"(d) : "l"(a),"l"(b))
#define PK2(d,lo,hi)  asm("mov.b64 %0,{%1,%2};" : "=l"(d) : "r"(__float_as_uint(lo)), "r"(__float_as_uint(hi)))
#define UPK2(lo,hi,s) do { unsigned _a,_b; asm("mov.b64 {%0,%1},%2;" : "=r"(_a),"=r"(_b) : "l"(s)); lo=__uint_as_float(_a); hi=__uint_as_float(_b); } while(0)

__device__ float g_Fp[BB*3*32];   // node partials from helper blocks 1..3
__device__ int   g_rowCtr[BB];    // zero-init; finisher resets
__device__ u64   g_acc;           // zero-init; packed (sum<<10 | count), self-resetting

// Grid (4, BB) x 512 = 128 blocks, single wave.
//  blk 1..3: pair partials for 640 scores at [FCH + (blk-1)*640): paired
//            sigmoid at node W=e^{x_k}: sig(a)+sig(b) = (2ab+pW)/(ab+pW+W^2).
//  blk 0   : finisher + pair worker for the small chunk [0,128). Overlapped
//            with helpers: preload all scores/labels, tiny pair chunk,
//            histogram -> rank-based maxDCG -> inv. Spin on row counter,
//            fold partials, warp-parallel DCT-II, packed-f32x2 Clenshaw
//            (4 pts/thread), row sum; one packed u64 atomic both accumulates
//            the mean (fixed-point, order-independent = deterministic) and
//            detects the last row; last row writes out. No fences on the hop.
__global__ __launch_bounds__(512, 2)
void fused(const float* __restrict__ yp, const float* __restrict__ yt,
           float* __restrict__ out) {
    int blk = blockIdx.x, b = blockIdx.y;
    int t = threadIdx.x, w = t >> 5, lane = t & 31;

    __shared__ float2 sP[HCH/2];
    __shared__ float sF[16*33];
    __shared__ float sFn[32];
    __shared__ float2 sC2[MC];        // coefs duplicated (lo==hi) for f32x2
    __shared__ float sRed[16];
    __shared__ unsigned long long sH[16];
    __shared__ int sOff[4];
    __shared__ float sInv;

    // node for this lane: x_k = HH*cos(pi(2k+1)/(2*MC)); lanes>=MC junk, unread
    float W  = __expf(HH * cospif((float)(2*lane + 1) * (1.0f/(2*MC))));
    float W2 = W * W;

    if (blk != 0) {
        // ------------- helper pair blocks: 640 scores each -------------
        const float* base = yp + b*NN + FCH + (blk - 1)*HCH;
        if (t < HCH/2) {
            float2 sc = ((const float2*)base)[t];
            float ea = __expf(sc.x), eb = __expf(sc.y);
            sP[t] = make_float2(ea + eb, 2.f*ea*eb);
        }
        __syncthreads();
        const float4* P4 = (const float4*)sP + w*10;   // 10 float4 = 20 pairs
        float acc = 0.f;
        #pragma unroll
        for (int i = 0; i < 10; i++) {
            float4 q = P4[i];
            acc = fmaf(fmaf(q.x, W, q.y),
                       __frcp_rn(fmaf(q.x, W, fmaf(0.5f, q.y, W2))), acc);
            acc = fmaf(fmaf(q.z, W, q.w),
                       __frcp_rn(fmaf(q.z, W, fmaf(0.5f, q.w, W2))), acc);
        }
        sF[w*33 + lane] = acc;
        __syncthreads();
        if (w == 0) {
            float F = 0.f;
            #pragma unroll
            for (int i = 0; i < 16; i++) F += sF[i*33 + lane];
            g_Fp[(b*3 + (blk - 1))*32 + lane] = F;
        }
        __syncthreads();
        if (t == 0) {
            __threadfence();
            atomicAdd(&g_rowCtr[b], 1);
        }
        return;
    }

    // -------------------- finisher block (also chunk [0,128)) --------------------
    float4 s4 = ((const float4*)(yp + b*NN))[t];    // all 2048 scores
    float4 l4 = ((const float4*)(yt + b*NN))[t];    // all 2048 labels
    int vv[4] = {(int)l4.x, (int)l4.y, (int)l4.z, (int)l4.w};

    // tiny pair chunk from registers (threads 0..31 own scores [0,128))
    if (t < 32) {
        float e0 = __expf(s4.x), e1 = __expf(s4.y);
        float e2 = __expf(s4.z), e3 = __expf(s4.w);
        sP[2*t]     = make_float2(e0 + e1, 2.f*e0*e1);
        sP[2*t + 1] = make_float2(e2 + e3, 2.f*e2*e3);
    }

    // packed label histogram (registers only)
    unsigned long long pk = (1ULL << (12*vv[0])) + (1ULL << (12*vv[1]))
                          + (1ULL << (12*vv[2])) + (1ULL << (12*vv[3]));
    #pragma unroll
    for (int o = 16; o; o >>= 1) pk += __shfl_xor_sync(0xffffffffu, pk, o);
    if (lane == 0) sH[w] = pk;
    __syncthreads();

    // pair loop over 64 pairs: 2 float4 per warp
    const float4* P4 = (const float4*)sP + w*2;
    float acc = 0.f;
    #pragma unroll
    for (int i = 0; i < 2; i++) {
        float4 q = P4[i];
        acc = fmaf(fmaf(q.x, W, q.y),
                   __frcp_rn(fmaf(q.x, W, fmaf(0.5f, q.y, W2))), acc);
        acc = fmaf(fmaf(q.z, W, q.w),
                   __frcp_rn(fmaf(q.z, W, fmaf(0.5f, q.w, W2))), acc);
    }
    sF[w*33 + lane] = acc;
    __syncthreads();

    if (w == 0) {            // fold own pair partials -> sFn
        float F = 0.f;
        #pragma unroll
        for (int i = 0; i < 16; i++) F += sF[i*33 + lane];
        sFn[lane] = F;
    } else if (w == 1) {     // fold histogram -> rank boundaries
        unsigned long long hh = (lane < 16) ? sH[lane] : 0ULL;
        #pragma unroll
        for (int o = 8; o; o >>= 1) hh += __shfl_xor_sync(0xffffffffu, hh, o);
        if (lane == 0) {
            int c4 = (int)((hh >> 48) & 0xFFF);
            int c3 = (int)((hh >> 36) & 0xFFF);
            int c2 = (int)((hh >> 24) & 0xFFF);
            int c1 = (int)((hh >> 12) & 0xFFF);
            sOff[0] = c4;  sOff[1] = c4 + c3;
            sOff[2] = c4 + c3 + c2;  sOff[3] = c4 + c3 + c2 + c1;
        }
    }
    __syncthreads();

    // rank-based maxDCG (rank r = n, 0-based); overlapped with helpers
    int B4 = sOff[0], B3 = sOff[1], B2 = sOff[2], B1 = sOff[3];
    float mdcg = 0.f;
    #pragma unroll
    for (int i = 0; i < 4; i++) {
        int n = t + i*512;
        int vr = 4 - (n >= B4) - (n >= B3) - (n >= B2) - (n >= B1);
        mdcg += __fdividef((float)((1 << vr) - 1), __log2f((float)(n + 2)));
    }
    #pragma unroll
    for (int o = 16; o; o >>= 1) mdcg += __shfl_xor_sync(0xffffffffu, mdcg, o);
    if (lane == 0) sRed[w] = mdcg;
    __syncthreads();
    if (t == 0) {
        float x = 0.f;
        #pragma unroll
        for (int i = 0; i < 16; i++) x += sRed[i];
        sInv = 1.0f / fmaxf(x, EPSF);
        // wait for this row's 3 helper blocks (all 128 blocks co-resident)
        while (*(volatile int*)&g_rowCtr[b] != 3) __nanosleep(64);
        g_rowCtr[b] = 0;                          // reset for next graph replay
    }
    __syncthreads();
    __threadfence();                              // acquire helper partials

    // fold helper partials into sFn
    if (t < 96) sF[t] = g_Fp[b*96 + t];
    __syncthreads();
    if (t < 32) {
        float F = sFn[t];
        #pragma unroll
        for (int i = 0; i < 3; i++) F += sF[i*32 + t];
        sFn[t] = F;
    }
    __syncthreads();

    // warp-parallel DCT-II: c_m = (2/MC) sum_k F_k cos(pi m(2k+1)/(2MC));
    // written duplicated into float2 for packed Clenshaw.
    float Fk = (lane < MC) ? sFn[lane] : 0.f;
    if (w < 14) {
        #pragma unroll
        for (int j = 0; j < 2; j++) {
            int m = w + 14*j;
            float term = Fk * cospif((float)(m*(2*lane + 1)) * (1.0f/(2*MC)));
            #pragma unroll
            for (int o = 16; o; o >>= 1) term += __shfl_xor_sync(0xffffffffu, term, o);
            if (lane == 0) {
                float cc = term * (2.0f/MC);
                if (m == 0) cc *= 0.5f;
                sC2[m] = make_float2(cc, cc);
            }
        }
    }
    __syncthreads();

    // packed-f32x2 Clenshaw at 4 points/thread (2 packs)
    float u0 = fminf(fmaxf(s4.x * (1.0f/HH), -1.f), 1.f);
    float u1 = fminf(fmaxf(s4.y * (1.0f/HH), -1.f), 1.f);
    float u2 = fminf(fmaxf(s4.z * (1.0f/HH), -1.f), 1.f);
    float u3 = fminf(fmaxf(s4.w * (1.0f/HH), -1.f), 1.f);
    u64 u01, u23, tu01, tu23;
    PK2(u01,  u0,      u1);
    PK2(u23,  u2,      u3);
    PK2(tu01, u0 + u0, u1 + u1);
    PK2(tu23, u2 + u2, u3 + u3);
    u64 y1a = 0ULL, y2a = 0ULL, y1b = 0ULL, y2b = 0ULL;
    #pragma unroll
    for (int m = MC - 1; m >= 1; m--) {
        u64 cd = *reinterpret_cast<const u64*>(&sC2[m]);
        u64 ta, tb;
        FMA2(ta, tu01, y1a, cd); SUB2(ta, ta, y2a); y2a = y1a; y1a = ta;
        FMA2(tb, tu23, y1b, cd); SUB2(tb, tb, y2b); y2b = y1b; y1b = tb;
    }
    u64 cd0 = *reinterpret_cast<const u64*>(&sC2[0]);
    u64 Fa, Fb;
    FMA2(Fa, u01, y1a, cd0); SUB2(Fa, Fa, y2a);
    FMA2(Fb, u23, y1b, cd0); SUB2(Fb, Fb, y2b);
    float F0, F1, F2, F3;
    UPK2(F0, F1, Fa);
    UPK2(F2, F3, Fb);

    float FF[4] = {F0, F1, F2, F3};
    float numer = 0.f;
    #pragma unroll
    for (int i = 0; i < 4; i++) {
        float gain = (float)((1 << vv[i]) - 1);
        numer += __fdividef(gain, __log2f(1.5f + FF[i]));   // pos = 0.5 + F
    }
    #pragma unroll
    for (int o = 16; o; o >>= 1) numer += __shfl_xor_sync(0xffffffffu, numer, o);
    if (lane == 0) sRed[w] = numer;
    __syncthreads();

    if (t == 0) {
        float x = 0.f;
        #pragma unroll
        for (int i = 0; i < 16; i++) x += sRed[i];
        // fixed-point row value: integer atomics commute -> deterministic sum.
        double val = (double)(x * sInv);
        u64 contrib = (u64)(val * 8796093022208.0 + 0.5);   // 2^43 scale
        u64 add = (contrib << 10) | 1ULL;
        u64 old = atomicAdd(&g_acc, add);
        if ((old & 1023ULL) == (u64)(BB - 1)) {             // 32nd (last) row
            u64 total = (old + add) >> 10;
            out[0] = (float)((double)total * (1.0 / (8796093022208.0 * BB)));
            g_acc = 0ULL;                                   // reset for replay
        }
    }
}

extern "C" void kernel_launch(void* const* d_in, const int* in_sizes, int n_in,
                              void* d_out, int out_size) {
    const float* yp = (const float*)d_in[0];
    const float* yt = (const float*)d_in[1];
    float* out = (float*)d_out;
    (void)in_sizes; (void)n_in; (void)out_size;

    dim3 g(4, BB);
    fused<<<g, 512>>>(yp, yt, out);
}